// round 1
// baseline (speedup 1.0000x reference)
#include <cuda_runtime.h>
#include <cstdint>

// StructureTensorEffect: B=4, C=3, H=W=1024.
// out[b,0] = sum_c (lum_c * s_u)^2 ; out[b,1] = sum_c (lum_c * s_v)^2 ;
// out[b,2] = sum_c (lum_c*s_u)(lum_c*s_v),  lum = (100,1,1).
//
// Key identity: px = u*W - 0.5 = x + OFF_U*sigma (pixel space), and the
// tap-combination kernels KU, KV are separable Sobel kernels:
//   KU = Du (x) Sv,  KV = Su (x) Dv, Du=(-.5,0,.5), Su=(.5,1,.5).
// Bilinear weights are separable too, and with integer x,y and per-batch
// constant sigma, floor/frac of the offsets are per-batch constants.
// => s_u = (Gx * Sy)(X), s_v = (Sx * Gy)(X) with 1D stencils of <=5 taps
// within offset range [-3,3].
//
// Border pixels (outer 3 rows/cols) use an exact 8-tap bilinear fallback
// matching the reference's clip() semantics.

#define Wd 1024
#define Hd 1024
#define TX 64
#define TY 16
#define TXH (TX + 6)   // 70
#define TYH (TY + 6)   // 22
#define NTHREADS 256

__device__ __forceinline__ int clampi(int v, int lo, int hi) {
    return min(max(v, lo), hi);
}

// Exact per-pixel path replicating reference clip semantics (border only).
__device__ void exact_pixel(const float* __restrict__ xb, float s,
                            int gx, int gy, float& A, float& Bv, float& Cv) {
    const float OU[8] = {-1.f,-1.f,-1.f, 0.f, 0.f, 1.f, 1.f, 1.f};
    const float OV[8] = {-1.f, 0.f, 1.f,-1.f, 1.f,-1.f, 0.f, 1.f};
    const float KU[8] = {-0.25f,-0.5f,-0.25f, 0.f, 0.f, 0.25f, 0.5f, 0.25f};
    const float KV[8] = {-0.25f, 0.f, 0.25f,-0.5f, 0.5f,-0.25f, 0.f, 0.25f};
    float su[3] = {0.f,0.f,0.f}, sv[3] = {0.f,0.f,0.f};
    #pragma unroll
    for (int t = 0; t < 8; ++t) {
        float px = (float)gx + OU[t] * s;
        float py = (float)gy + OV[t] * s;
        float x0f = floorf(px), y0f = floorf(py);
        float fx = px - x0f, fy = py - y0f;
        int x0 = clampi((int)x0f, 0, Wd - 1);
        int x1 = min(x0 + 1, Wd - 1);
        int y0 = clampi((int)y0f, 0, Hd - 1);
        int y1 = min(y0 + 1, Hd - 1);
        float w00 = (1.f - fx) * (1.f - fy);
        float w01 = fx * (1.f - fy);
        float w10 = (1.f - fx) * fy;
        float w11 = fx * fy;
        #pragma unroll
        for (int c = 0; c < 3; ++c) {
            const float* p = xb + (size_t)c * Hd * Wd;
            float bil = w00 * __ldg(&p[y0 * Wd + x0]) + w01 * __ldg(&p[y0 * Wd + x1])
                      + w10 * __ldg(&p[y1 * Wd + x0]) + w11 * __ldg(&p[y1 * Wd + x1]);
            su[c] += KU[t] * bil;
            sv[c] += KV[t] * bil;
        }
    }
    A = 0.f; Bv = 0.f; Cv = 0.f;
    #pragma unroll
    for (int c = 0; c < 3; ++c) {
        float l = (c == 0) ? 100.f : 1.f;
        float a = su[c] * l, b = sv[c] * l;
        A += a * a; Bv += b * b; Cv += a * b;
    }
}

__global__ __launch_bounds__(NTHREADS)
void st_kernel(const float* __restrict__ x, const float* __restrict__ sigma,
               float* __restrict__ out) {
    __shared__ float raw[TYH][TXH];
    __shared__ float sS[TY][TXH];   // vertical smooth   (Sy * X)
    __shared__ float sG[TY][TXH];   // vertical derivative (Gy * X)
    __shared__ float wts[8];

    const int b   = blockIdx.z;
    const int bx0 = blockIdx.x * TX;
    const int by0 = blockIdx.y * TY;
    const int tid = threadIdx.x;

    if (tid == 0) {
        float s  = __ldg(&sigma[b]);
        float dm = -s; float jmf = floorf(dm); float fm = dm - jmf;
        float dp =  s; float jpf = floorf(dp); float fp = dp - jpf;
        wts[0] = jmf;            wts[1] = jpf;
        wts[2] = 0.5f * (1.f - fm);  wts[3] = 0.5f * fm;
        wts[4] = 0.5f * (1.f - fp);  wts[5] = 0.5f * fp;
        wts[6] = s;
    }
    __syncthreads();

    const float s   = wts[6];
    const int   jm  = (int)wts[0];   // in [-3,-1]
    const int   jp  = (int)wts[1];   // in [ 0, 2]
    const float wm0 = wts[2], wm1 = wts[3];
    const float wp0 = wts[4], wp1 = wts[5];

    const int tx  = tid & 63;       // 0..63
    const int tyq = tid >> 6;       // 0..3  -> rows tyq*4 + k

    float accA[4] = {0.f,0.f,0.f,0.f};
    float accB[4] = {0.f,0.f,0.f,0.f};
    float accC[4] = {0.f,0.f,0.f,0.f};

    const float* xb = x + (size_t)b * 3 * Hd * Wd;

    #pragma unroll
    for (int c = 0; c < 3; ++c) {
        const float* plane = xb + (size_t)c * Hd * Wd;
        const float lq = (c == 0) ? 10000.f : 1.f;

        // ---- load raw tile (with 3-wide halo, clamped) ----
        for (int i = tid; i < TYH * TXH; i += NTHREADS) {
            int rr = i / TXH, cc = i - rr * TXH;
            int gy = clampi(by0 - 3 + rr, 0, Hd - 1);
            int gx = clampi(bx0 - 3 + cc, 0, Wd - 1);
            raw[rr][cc] = __ldg(&plane[gy * Wd + gx]);
        }
        __syncthreads();

        // ---- vertical pass: Sy and Gy for all rows, incl. x-halo cols ----
        for (int i = tid; i < TY * TXH; i += NTHREADS) {
            int r = i / TXH, cc = i - r * TXH;
            float vm0 = raw[r + 3 + jm][cc];
            float vm1 = raw[r + 4 + jm][cc];
            float vp0 = raw[r + 3 + jp][cc];
            float vp1 = raw[r + 4 + jp][cc];
            float vc  = raw[r + 3][cc];
            float mpart = wm0 * vm0 + wm1 * vm1;
            float ppart = wp0 * vp0 + wp1 * vp1;
            sS[r][cc] = vc + mpart + ppart;
            sG[r][cc] = ppart - mpart;
        }
        __syncthreads();

        // ---- horizontal pass + accumulate quadratic outputs ----
        const int cx = tx + 3;
        #pragma unroll
        for (int k = 0; k < 4; ++k) {
            int r = tyq * 4 + k;
            float su = wp0 * sS[r][cx + jp] + wp1 * sS[r][cx + 1 + jp]
                     - wm0 * sS[r][cx + jm] - wm1 * sS[r][cx + 1 + jm];
            float sv = sG[r][cx]
                     + wm0 * sG[r][cx + jm] + wm1 * sG[r][cx + 1 + jm]
                     + wp0 * sG[r][cx + jp] + wp1 * sG[r][cx + 1 + jp];
            accA[k] += lq * su * su;
            accB[k] += lq * sv * sv;
            accC[k] += lq * su * sv;
        }
        __syncthreads();
    }

    // ---- write out; exact fallback at image borders ----
    float* out0 = out + (size_t)(b * 3 + 0) * Hd * Wd;
    float* out1 = out + (size_t)(b * 3 + 1) * Hd * Wd;
    float* out2 = out + (size_t)(b * 3 + 2) * Hd * Wd;

    #pragma unroll
    for (int k = 0; k < 4; ++k) {
        int gx = bx0 + tx;
        int gy = by0 + tyq * 4 + k;
        float A = accA[k], Bv = accB[k], Cv = accC[k];
        bool interior = (gx >= 3) && (gx < Wd - 3) && (gy >= 3) && (gy < Hd - 3);
        if (!interior) {
            exact_pixel(xb, s, gx, gy, A, Bv, Cv);
        }
        size_t o = (size_t)gy * Wd + gx;
        out0[o] = A;
        out1[o] = Bv;
        out2[o] = Cv;
    }
}

extern "C" void kernel_launch(void* const* d_in, const int* in_sizes, int n_in,
                              void* d_out, int out_size) {
    const float* x     = (const float*)d_in[0];
    const float* sigma = (const float*)d_in[1];
    float* out = (float*)d_out;
    int B = in_sizes[1];               // sigma element count == batch
    dim3 grid(Wd / TX, Hd / TY, B);
    st_kernel<<<grid, NTHREADS>>>(x, sigma, out);
}

// round 2
// speedup vs baseline: 1.7457x; 1.7457x over previous
#include <cuda_runtime.h>
#include <cstdint>

// StructureTensorEffect, B=4, C=3, H=W=1024.
// Separable form: s_u = Gx*Sy, s_v = Sx*Gy with per-batch-constant fractional
// stencils. sigma in [0.5,2.5) => JP = floor(sigma) in {0,1,2}, JM = -JP-1
// (exact-integer sigma folds in via fm = 1-fp). Kernel templated on JP so all
// stencil offsets are compile-time constants.
//
// Phase 1 (vertical): per-thread float4 column strip, rolling register window
//   over gmem rows -> vS, vG float4 -> smem. No raw tile staging.
// Phase 2 (horizontal): 3 aligned LDS.128 per 4-pixel window per array,
//   static tap selection, quadratic accumulation, float4 stores.
// Border pixels (outer 3) use an exact 8-tap bilinear fallback.

#define Wd 1024
#define Hd 1024
#define TX 128
#define TY 16
#define HX 4
#define SW (TX + 2*HX)            // 136 floats per smem row
#define NTH 256
#define NSTRIP (SW/4)             // 34 float4 strips
#define CHUNK 8
#define NCHUNK (TY/CHUNK)         // 2
#define NVTASK (NSTRIP*NCHUNK*3)  // 204
#define HW (Hd*Wd)
#define SMEM_FLOATS (3*TY*SW)     // per array
#define SMEM_BYTES (2*SMEM_FLOATS*4)

__device__ __forceinline__ int clampi(int v, int lo, int hi) {
    return min(max(v, lo), hi);
}

// Exact per-pixel path replicating reference clip semantics (border only).
__device__ __noinline__ void exact_pixel(const float* __restrict__ xb, float s,
                                         int gx, int gy,
                                         float& A, float& Bv, float& Cv) {
    const float OU[8] = {-1.f,-1.f,-1.f, 0.f, 0.f, 1.f, 1.f, 1.f};
    const float OV[8] = {-1.f, 0.f, 1.f,-1.f, 1.f,-1.f, 0.f, 1.f};
    const float KU[8] = {-0.25f,-0.5f,-0.25f, 0.f, 0.f, 0.25f, 0.5f, 0.25f};
    const float KV[8] = {-0.25f, 0.f, 0.25f,-0.5f, 0.5f,-0.25f, 0.f, 0.25f};
    float su[3] = {0.f,0.f,0.f}, sv[3] = {0.f,0.f,0.f};
    #pragma unroll
    for (int t = 0; t < 8; ++t) {
        float px = (float)gx + OU[t] * s;
        float py = (float)gy + OV[t] * s;
        float x0f = floorf(px), y0f = floorf(py);
        float fx = px - x0f, fy = py - y0f;
        int x0 = clampi((int)x0f, 0, Wd - 1);
        int x1 = min(x0 + 1, Wd - 1);
        int y0 = clampi((int)y0f, 0, Hd - 1);
        int y1 = min(y0 + 1, Hd - 1);
        float w00 = (1.f - fx) * (1.f - fy);
        float w01 = fx * (1.f - fy);
        float w10 = (1.f - fx) * fy;
        float w11 = fx * fy;
        #pragma unroll
        for (int c = 0; c < 3; ++c) {
            const float* p = xb + (size_t)c * HW;
            float bil = w00 * __ldg(&p[y0 * Wd + x0]) + w01 * __ldg(&p[y0 * Wd + x1])
                      + w10 * __ldg(&p[y1 * Wd + x0]) + w11 * __ldg(&p[y1 * Wd + x1]);
            su[c] += KU[t] * bil;
            sv[c] += KV[t] * bil;
        }
    }
    A = 0.f; Bv = 0.f; Cv = 0.f;
    #pragma unroll
    for (int c = 0; c < 3; ++c) {
        float l = (c == 0) ? 100.f : 1.f;
        float a = su[c] * l, b = sv[c] * l;
        A += a * a; Bv += b * b; Cv += a * b;
    }
}

template<int JP>
__device__ __forceinline__ void run_tile(const float* __restrict__ xb, float s,
                                         float* __restrict__ smS,
                                         float* __restrict__ smG,
                                         float* __restrict__ out,
                                         int b, int bx0, int by0, int tid) {
    // weights: fp = s - JP in [0,1); fm = 1 - fp
    const float fp  = s - (float)JP;
    const float wp0 = 0.5f * (1.f - fp);
    const float wp1 = 0.5f * fp;
    const float wm0 = wp1;            // 0.5*(1-fm) = 0.5*fp
    const float wm1 = wp0;            // 0.5*fm     = 0.5*(1-fp)

    // ---------------- Phase 1: vertical stencil -> smem ----------------
    if (tid < NVTASK) {
        const int c     = tid / (NSTRIP * NCHUNK);
        const int rem   = tid - c * (NSTRIP * NCHUNK);
        const int chunk = rem / NSTRIP;
        const int strip = rem - chunk * NSTRIP;

        const float* plane = xb + (size_t)c * HW;
        int gx0 = bx0 - HX + strip * 4;
        gx0 = clampi(gx0, 0, Wd - 4);

        const int ybase = by0 + chunk * CHUNK;

        constexpr int WIN = 2 * JP + 3;
        float4 win[WIN];
        #pragma unroll
        for (int r = -JP - 1; r <= JP; ++r) {
            int gy = clampi(ybase + r, 0, Hd - 1);
            win[r + JP + 1] = __ldg((const float4*)(plane + (size_t)gy * Wd + gx0));
        }

        float* sSrow = smS + (size_t)(c * TY + chunk * CHUNK) * SW + strip * 4;
        float* sGrow = smG + (size_t)(c * TY + chunk * CHUNK) * SW + strip * 4;

        #pragma unroll
        for (int j = 0; j < CHUNK; ++j) {
            int gy = clampi(ybase + j + JP + 1, 0, Hd - 1);
            win[(j + 2 * JP + 2) % WIN] = __ldg((const float4*)(plane + (size_t)gy * Wd + gx0));

            float4 m0 = win[(j)              % WIN];
            float4 m1 = win[(j + 1)          % WIN];
            float4 ce = win[(j + JP + 1)     % WIN];
            float4 p0 = win[(j + 2 * JP + 1) % WIN];
            float4 p1 = win[(j + 2 * JP + 2) % WIN];

            float4 vs, vg;
            {
                float mpx = wm0 * m0.x + wm1 * m1.x;
                float mpy = wm0 * m0.y + wm1 * m1.y;
                float mpz = wm0 * m0.z + wm1 * m1.z;
                float mpw = wm0 * m0.w + wm1 * m1.w;
                float ppx = wp0 * p0.x + wp1 * p1.x;
                float ppy = wp0 * p0.y + wp1 * p1.y;
                float ppz = wp0 * p0.z + wp1 * p1.z;
                float ppw = wp0 * p0.w + wp1 * p1.w;
                vs.x = ce.x + mpx + ppx;  vg.x = ppx - mpx;
                vs.y = ce.y + mpy + ppy;  vg.y = ppy - mpy;
                vs.z = ce.z + mpz + ppz;  vg.z = ppz - mpz;
                vs.w = ce.w + mpw + ppw;  vg.w = ppw - mpw;
            }
            *(float4*)(sSrow + (size_t)j * SW) = vs;
            *(float4*)(sGrow + (size_t)j * SW) = vg;
        }
    }
    __syncthreads();

    // ---------------- Phase 2: horizontal stencil + quadratics ----------------
    const int tx5 = tid & 31;        // col group
    const int tyh = tid >> 5;        // 0..7
    const int xl  = tx5 * 4;         // local output col 0..124
    const int r0  = tyh * 2;         // two rows per thread

    float accA[2][4], accB[2][4], accC[2][4];
    #pragma unroll
    for (int rr = 0; rr < 2; ++rr)
        #pragma unroll
        for (int i = 0; i < 4; ++i) { accA[rr][i] = 0.f; accB[rr][i] = 0.f; accC[rr][i] = 0.f; }

    constexpr int dM = 3 - JP;   // JM + 4
    constexpr int dP = 4 + JP;

    #pragma unroll
    for (int c = 0; c < 3; ++c) {
        const float lq = (c == 0) ? 10000.f : 1.f;
        #pragma unroll
        for (int rr = 0; rr < 2; ++rr) {
            const int lr = r0 + rr;
            const float* Sp = smS + (size_t)(c * TY + lr) * SW + xl;   // window base (= pixel - 4)
            const float* Gp = smG + (size_t)(c * TY + lr) * SW + xl;
            float4 a0 = *(const float4*)(Sp);
            float4 a1 = *(const float4*)(Sp + 4);
            float4 a2 = *(const float4*)(Sp + 8);
            float4 b0 = *(const float4*)(Gp);
            float4 b1 = *(const float4*)(Gp + 4);
            float4 b2 = *(const float4*)(Gp + 8);
            float sw[12] = {a0.x,a0.y,a0.z,a0.w, a1.x,a1.y,a1.z,a1.w, a2.x,a2.y,a2.z,a2.w};
            float gw[12] = {b0.x,b0.y,b0.z,b0.w, b1.x,b1.y,b1.z,b1.w, b2.x,b2.y,b2.z,b2.w};
            #pragma unroll
            for (int i = 0; i < 4; ++i) {
                float su = wp0 * sw[i + dP] + wp1 * sw[i + dP + 1]
                         - wm0 * sw[i + dM] - wm1 * sw[i + dM + 1];
                float sv = gw[i + 4]
                         + wm0 * gw[i + dM] + wm1 * gw[i + dM + 1]
                         + wp0 * gw[i + dP] + wp1 * gw[i + dP + 1];
                accA[rr][i] += lq * su * su;
                accB[rr][i] += lq * sv * sv;
                accC[rr][i] += lq * su * sv;
            }
        }
    }

    // ---------------- Output ----------------
    float* out0 = out + ((size_t)b * 3 + 0) * HW;
    float* out1 = out + ((size_t)b * 3 + 1) * HW;
    float* out2 = out + ((size_t)b * 3 + 2) * HW;
    const int gxg = bx0 + xl;
    const bool xint = (gxg >= 3) && (gxg + 3 <= Wd - 4);

    #pragma unroll
    for (int rr = 0; rr < 2; ++rr) {
        const int gy = by0 + r0 + rr;
        const bool yint = (gy >= 3) && (gy <= Hd - 4);
        const size_t o = (size_t)gy * Wd + gxg;
        if (xint && yint) {
            *(float4*)(out0 + o) = make_float4(accA[rr][0], accA[rr][1], accA[rr][2], accA[rr][3]);
            *(float4*)(out1 + o) = make_float4(accB[rr][0], accB[rr][1], accB[rr][2], accB[rr][3]);
            *(float4*)(out2 + o) = make_float4(accC[rr][0], accC[rr][1], accC[rr][2], accC[rr][3]);
        } else {
            #pragma unroll
            for (int i = 0; i < 4; ++i) {
                int gx = gxg + i;
                float A = accA[rr][i], Bv = accB[rr][i], Cv = accC[rr][i];
                if (!(yint && gx >= 3 && gx <= Wd - 4)) {
                    exact_pixel(xb, s, gx, gy, A, Bv, Cv);
                }
                out0[o + i] = A;
                out1[o + i] = Bv;
                out2[o + i] = Cv;
            }
        }
    }
}

__global__ __launch_bounds__(NTH, 3)
void st2_kernel(const float* __restrict__ x, const float* __restrict__ sigma,
                float* __restrict__ out) {
    extern __shared__ float sm[];
    float* smS = sm;
    float* smG = sm + SMEM_FLOATS;

    const int b   = blockIdx.z;
    const int bx0 = blockIdx.x * TX;
    const int by0 = blockIdx.y * TY;
    const int tid = threadIdx.x;

    const float s = __ldg(&sigma[b]);
    const int jp = clampi((int)floorf(s), 0, 2);
    const float* xb = x + (size_t)b * 3 * HW;

    if (jp == 0)      run_tile<0>(xb, s, smS, smG, out, b, bx0, by0, tid);
    else if (jp == 1) run_tile<1>(xb, s, smS, smG, out, b, bx0, by0, tid);
    else              run_tile<2>(xb, s, smS, smG, out, b, bx0, by0, tid);
}

extern "C" void kernel_launch(void* const* d_in, const int* in_sizes, int n_in,
                              void* d_out, int out_size) {
    const float* x     = (const float*)d_in[0];
    const float* sigma = (const float*)d_in[1];
    float* out = (float*)d_out;
    int B = in_sizes[1];

    static_assert(SMEM_BYTES == 52224, "smem size");
    cudaFuncSetAttribute(st2_kernel, cudaFuncAttributeMaxDynamicSharedMemorySize, SMEM_BYTES);

    dim3 grid(Wd / TX, Hd / TY, B);
    st2_kernel<<<grid, NTH, SMEM_BYTES>>>(x, sigma, out);
}